// round 1
// baseline (speedup 1.0000x reference)
#include <cuda_runtime.h>
#include <cuda_fp16.h>
#include <cstdint>

#define NN    8192
#define INF_  256
#define OUTF  128
#define GROWS 160     // rows of G^T (columns of G); row 128 = w, rows 129..159 stay 0

// G^T scratch: [GROWS][NN] halves. Zero-initialized at module load; we only ever
// write rows 0..128, pad rows remain zero forever (deterministic).
static __device__ __half g_buf[GROWS * NN];

// ---------------------------------------------------------------------------
// Kernel A: h = feat@W + b ; w = exp(h . a2w + a2b) ; G^T[c][i] = half(w_i*h_ic),
//           G^T[128][i] = half(w_i)
// ---------------------------------------------------------------------------
__global__ void __launch_bounds__(256) proj_kernel(
    const float* __restrict__ feat, const float* __restrict__ W,
    const float* __restrict__ bias, const float* __restrict__ a2w,
    const float* __restrict__ a2b)
{
    __shared__ float Fs[64][36];
    __shared__ float Ws[32][128];
    __shared__ float red[64][17];
    __shared__ float wrow[64];
    __shared__ __half T[129][72];   // transpose staging, 144B row stride (16B aligned)

    const int tid   = threadIdx.x;
    const int m_idx = tid >> 4;      // 0..15
    const int n_idx = tid & 15;      // 0..15
    const int row0  = m_idx * 4;
    const int col0  = n_idx * 8;
    const int R     = blockIdx.x * 64;

    float acc[4][8];
    #pragma unroll
    for (int i = 0; i < 4; i++)
        #pragma unroll
        for (int j = 0; j < 8; j++) acc[i][j] = 0.f;

    for (int k0 = 0; k0 < INF_; k0 += 32) {
        #pragma unroll
        for (int c = tid; c < 512; c += 256) {
            int r = c >> 3, kq = (c & 7) << 2;
            float4 v = *(const float4*)(feat + (size_t)(R + r) * INF_ + k0 + kq);
            Fs[r][kq] = v.x; Fs[r][kq + 1] = v.y; Fs[r][kq + 2] = v.z; Fs[r][kq + 3] = v.w;
        }
        #pragma unroll
        for (int c = tid; c < 1024; c += 256) {
            int r = c >> 5, nq = (c & 31) << 2;
            *(float4*)&Ws[r][nq] = *(const float4*)(W + (size_t)(k0 + r) * OUTF + nq);
        }
        __syncthreads();
        #pragma unroll
        for (int kk = 0; kk < 32; kk++) {
            float a[4];
            #pragma unroll
            for (int i = 0; i < 4; i++) a[i] = Fs[row0 + i][kk];
            float4 b0 = *(float4*)&Ws[kk][col0];
            float4 b1 = *(float4*)&Ws[kk][col0 + 4];
            float bb[8] = {b0.x, b0.y, b0.z, b0.w, b1.x, b1.y, b1.z, b1.w};
            #pragma unroll
            for (int i = 0; i < 4; i++)
                #pragma unroll
                for (int j = 0; j < 8; j++) acc[i][j] += a[i] * bb[j];
        }
        __syncthreads();
    }

    // bias + a2 partial dot
    float bv[8], aw[8];
    #pragma unroll
    for (int j = 0; j < 8; j++) { bv[j] = bias[col0 + j]; aw[j] = a2w[col0 + j]; }
    #pragma unroll
    for (int i = 0; i < 4; i++) {
        float p = 0.f;
        #pragma unroll
        for (int j = 0; j < 8; j++) { acc[i][j] += bv[j]; p += acc[i][j] * aw[j]; }
        red[row0 + i][n_idx] = p;
    }
    __syncthreads();
    if (tid < 64) {
        float s = 0.f;
        #pragma unroll
        for (int j = 0; j < 16; j++) s += red[tid][j];
        wrow[tid] = expf(s + a2b[0]);
    }
    __syncthreads();

    // transpose into T, then coalesced STG of G^T
    #pragma unroll
    for (int i = 0; i < 4; i++) {
        float w = wrow[row0 + i];
        #pragma unroll
        for (int j = 0; j < 8; j++)
            T[col0 + j][row0 + i] = __float2half(acc[i][j] * w);
        if (n_idx == 0) T[128][row0 + i] = __float2half(w);
    }
    __syncthreads();
    #pragma unroll
    for (int c = tid; c < 129 * 8; c += 256) {
        int rr = c >> 3, off = (c & 7) << 3;       // 8 halves = 16B chunks
        *(uint4*)(g_buf + (size_t)rr * NN + R + off) = *(const uint4*)&T[rr][off];
    }
}

// ---------------------------------------------------------------------------
// Kernel B: C[64,160] tile = adj_fp16[64,8192] @ G[8192,160] via mma.sync,
//           epilogue out = num/den
// ---------------------------------------------------------------------------
#define BM 64
#define BK 64
#define NT (NN / BK)   // 128 K-tiles

__global__ void __launch_bounds__(256) agg_kernel(
    const int* __restrict__ adj, float* __restrict__ out)
{
    extern __shared__ char smem[];
    __half* As = (__half*)smem;                               // [2][64][72]
    __half* Bs = (__half*)(smem + 2 * 64 * 72 * 2);           // [2][160][72] (n-major)
    float* dens = (float*)(smem + 2 * 64 * 72 * 2 + 2 * 160 * 72 * 2);

    const int tid  = threadIdx.x;
    const int lane = tid & 31;
    const int warp = tid >> 5;
    const int wm   = warp & 3;   // 0..3 -> m16 slice
    const int wn   = warp >> 2;  // 0..1 -> n80 slice
    const int R    = blockIdx.x * BM;

    float c[10][4];
    #pragma unroll
    for (int f = 0; f < 10; f++)
        #pragma unroll
        for (int j = 0; j < 4; j++) c[f][j] = 0.f;

    int4 areg[4];

    auto loadA = [&](int kt) {
        #pragma unroll
        for (int i = 0; i < 4; i++) {
            int cc = tid + i * 256;
            int r = cc >> 4, k4 = (cc & 15) << 2;
            areg[i] = *(const int4*)(adj + (size_t)(R + r) * NN + kt * BK + k4);
        }
    };
    auto stsA = [&](int buf) {
        #pragma unroll
        for (int i = 0; i < 4; i++) {
            int cc = tid + i * 256;
            int r = cc >> 4, k4 = (cc & 15) << 2;
            uint32_t p0 = (areg[i].x > 0 ? 0x3C00u : 0u) | ((areg[i].y > 0 ? 0x3C00u : 0u) << 16);
            uint32_t p1 = (areg[i].z > 0 ? 0x3C00u : 0u) | ((areg[i].w > 0 ? 0x3C00u : 0u) << 16);
            *(uint2*)(As + buf * 64 * 72 + r * 72 + k4) = make_uint2(p0, p1);
        }
    };
    auto issueB = [&](int kt, int buf) {
        #pragma unroll
        for (int i = 0; i < 5; i++) {
            int cc = tid + i * 256;
            int n = cc >> 3, koff = (cc & 7) << 3;
            const __half* src = g_buf + (size_t)n * NN + kt * BK + koff;
            uint32_t dst = (uint32_t)__cvta_generic_to_shared(Bs + buf * 160 * 72 + n * 72 + koff);
            asm volatile("cp.async.cg.shared.global [%0], [%1], 16;\n" :: "r"(dst), "l"(src));
        }
        asm volatile("cp.async.commit_group;\n" ::: "memory");
    };
    auto compute = [&](int buf) {
        const __half* Ab = As + buf * 64 * 72;
        const __half* Bb = Bs + buf * 160 * 72;
        #pragma unroll
        for (int kk = 0; kk < 4; kk++) {
            uint32_t a0, a1, a2, a3;
            {
                int r = wm * 16 + (lane & 15);
                int col = kk * 16 + ((lane >> 4) << 3);
                uint32_t addr = (uint32_t)__cvta_generic_to_shared(Ab + r * 72 + col);
                asm volatile("ldmatrix.sync.aligned.m8n8.x4.shared.b16 {%0,%1,%2,%3}, [%4];"
                             : "=r"(a0), "=r"(a1), "=r"(a2), "=r"(a3) : "r"(addr));
            }
            #pragma unroll
            for (int fp = 0; fp < 5; fp++) {
                int n = wn * 80 + fp * 16 + ((lane >> 4) << 3) + (lane & 7);
                int k = kk * 16 + (((lane >> 3) & 1) << 3);
                uint32_t addr = (uint32_t)__cvta_generic_to_shared(Bb + n * 72 + k);
                uint32_t b0, b1, b2, b3;
                asm volatile("ldmatrix.sync.aligned.m8n8.x4.shared.b16 {%0,%1,%2,%3}, [%4];"
                             : "=r"(b0), "=r"(b1), "=r"(b2), "=r"(b3) : "r"(addr));
                asm volatile("mma.sync.aligned.m16n8k16.row.col.f32.f16.f16.f32 "
                             "{%0,%1,%2,%3}, {%4,%5,%6,%7}, {%8,%9}, {%0,%1,%2,%3};"
                             : "+f"(c[2 * fp][0]), "+f"(c[2 * fp][1]), "+f"(c[2 * fp][2]), "+f"(c[2 * fp][3])
                             : "r"(a0), "r"(a1), "r"(a2), "r"(a3), "r"(b0), "r"(b1));
                asm volatile("mma.sync.aligned.m16n8k16.row.col.f32.f16.f16.f32 "
                             "{%0,%1,%2,%3}, {%4,%5,%6,%7}, {%8,%9}, {%0,%1,%2,%3};"
                             : "+f"(c[2 * fp + 1][0]), "+f"(c[2 * fp + 1][1]), "+f"(c[2 * fp + 1][2]), "+f"(c[2 * fp + 1][3])
                             : "r"(a0), "r"(a1), "r"(a2), "r"(a3), "r"(b2), "r"(b3));
            }
        }
    };

    // prologue
    loadA(0);
    issueB(0, 0);
    stsA(0);
    asm volatile("cp.async.wait_group 0;\n" ::: "memory");
    __syncthreads();

    for (int t = 0; t < NT; t++) {
        int cur = t & 1;
        if (t + 1 < NT) {
            loadA(t + 1);
            issueB(t + 1, cur ^ 1);
        }
        compute(cur);
        if (t + 1 < NT) {
            stsA(cur ^ 1);
            asm volatile("cp.async.wait_group 0;\n" ::: "memory");
        }
        __syncthreads();
    }

    // epilogue: den = column 128 (warp wn==1, frag 6, lane%4==0)
    const int r0 = wm * 16 + (lane >> 2);
    const int r1 = r0 + 8;
    if (wn == 1 && (lane & 3) == 0) {
        dens[r0] = c[6][0];
        dens[r1] = c[6][2];
    }
    __syncthreads();
    const float d0 = dens[r0], d1 = dens[r1];
    const int nb = wn * 80;
    #pragma unroll
    for (int f = 0; f < 10; f++) {
        int col = nb + f * 8 + ((lane & 3) << 1);
        if (col < OUTF) {
            float2 v0 = make_float2(c[f][0] / d0, c[f][1] / d0);
            float2 v1 = make_float2(c[f][2] / d1, c[f][3] / d1);
            *(float2*)(out + (size_t)(R + r0) * OUTF + col) = v0;
            *(float2*)(out + (size_t)(R + r1) * OUTF + col) = v1;
        }
    }
}

// ---------------------------------------------------------------------------
extern "C" void kernel_launch(void* const* d_in, const int* in_sizes, int n_in,
                              void* d_out, int out_size) {
    (void)in_sizes; (void)n_in; (void)out_size;
    const float* feat = (const float*)d_in[0];
    const int*   adj  = (const int*)d_in[1];
    const float* W    = (const float*)d_in[2];
    const float* b    = (const float*)d_in[3];
    // d_in[4], d_in[5] (a1_w, a1_b) cancel in the softmax and are unused.
    const float* a2w  = (const float*)d_in[6];
    const float* a2b  = (const float*)d_in[7];
    float* out = (float*)d_out;

    proj_kernel<<<NN / 64, 256>>>(feat, W, b, a2w, a2b);

    const int smem_bytes = 2 * 64 * 72 * 2 + 2 * 160 * 72 * 2 + 64 * 4;  // 64768
    cudaFuncSetAttribute(agg_kernel, cudaFuncAttributeMaxDynamicSharedMemorySize, smem_bytes);
    agg_kernel<<<NN / BM, 256, smem_bytes>>>(adj, out);
}

// round 5
// speedup vs baseline: 1.6255x; 1.6255x over previous
#include <cuda_runtime.h>
#include <cuda_fp16.h>
#include <cstdint>

#define NN    8192
#define INF_  256
#define OUTF  128
#define GROWS 160     // rows of G^T; row 128 = w, rows 129..159 stay 0
#define KS    4       // K-split for agg
#define TPK   (128 / KS)   // 32 K-tiles of 64 per CTA
#define WSTR  132     // ws row stride in floats (divisible by 4 -> 16B aligned rows)

// G^T scratch: [GROWS][NN] halves. Zero-initialized at module load; rows 129..159
// are never written (deterministic zeros).
static __device__ __half g_buf[GROWS * NN];
// Partial sums workspace: ws[split][row][col], col stride WSTR (col 128 = den).
static __device__ float ws[(size_t)KS * NN * WSTR];

// ---------------------------------------------------------------------------
// Kernel A (fp16 MMA): h = feat@W + b ; w = exp(h.a2w + a2b);
// G^T[c][i] = half(w_i * h_ic); G^T[128][i] = half(w_i)
// ---------------------------------------------------------------------------
__global__ void __launch_bounds__(256) proj_kernel(
    const float* __restrict__ feat, const float* __restrict__ W,
    const float* __restrict__ bias, const float* __restrict__ a2w,
    const float* __restrict__ a2b)
{
    extern __shared__ char sm[];
    __half* Fh = (__half*)sm;                       // [64][264] halves (33792 B)
    float*  Wf = (float*)sm;                        // [64][132] floats (alias, staging)
    __half* T  = (__half*)sm;                       // [129][72] halves (alias, epilogue)
    __half* Wt = (__half*)(sm + 33792);             // [128][264] halves (67584 B)
    float*  red = (float*)(sm + 33792 + 67584);     // [64][8]
    float*  wrow = red + 64 * 8;                    // [64]

    const int tid  = threadIdx.x;
    const int lane = tid & 31;
    const int warp = tid >> 5;
    const int wm   = warp & 3;   // m16 slice
    const int wn   = warp >> 2;  // n64 slice
    const int R    = blockIdx.x * 64;

    // ---- W^T into Wt (fp16), 4 k-chunks through Wf staging ----
    for (int k0 = 0; k0 < INF_; k0 += 64) {
        #pragma unroll
        for (int i = 0; i < 8; i++) {
            int cc = tid + i * 256;
            int r = cc >> 5, n4 = (cc & 31) << 2;
            *(float4*)(Wf + r * 132 + n4) = *(const float4*)(W + (size_t)(k0 + r) * OUTF + n4);
        }
        __syncthreads();
        #pragma unroll
        for (int i = 0; i < 8; i++) {
            int cc = tid + i * 256;
            int n = cc >> 4, kq = (cc & 15) << 2;
            float f0 = Wf[(kq + 0) * 132 + n];
            float f1 = Wf[(kq + 1) * 132 + n];
            float f2 = Wf[(kq + 2) * 132 + n];
            float f3 = Wf[(kq + 3) * 132 + n];
            *(__half2*)(Wt + n * 264 + k0 + kq)     = __floats2half2_rn(f0, f1);
            *(__half2*)(Wt + n * 264 + k0 + kq + 2) = __floats2half2_rn(f2, f3);
        }
        __syncthreads();
    }

    // ---- feat -> Fh (fp16) ----
    #pragma unroll
    for (int i = 0; i < 16; i++) {
        int cc = tid + i * 256;
        int r = cc >> 6, c4 = (cc & 63) << 2;
        float4 v = *(const float4*)(feat + (size_t)(R + r) * INF_ + c4);
        *(__half2*)(Fh + r * 264 + c4)     = __floats2half2_rn(v.x, v.y);
        *(__half2*)(Fh + r * 264 + c4 + 2) = __floats2half2_rn(v.z, v.w);
    }
    __syncthreads();

    // ---- MMA: h[64,128] = Fh[64,256] @ Wt^T ----
    float c[8][4];
    #pragma unroll
    for (int f = 0; f < 8; f++)
        #pragma unroll
        for (int j = 0; j < 4; j++) c[f][j] = 0.f;

    #pragma unroll
    for (int kk = 0; kk < 16; kk++) {
        uint32_t a0, a1, a2, a3;
        {
            int r = wm * 16 + (lane & 15);
            int col = kk * 16 + ((lane >> 4) << 3);
            uint32_t addr = (uint32_t)__cvta_generic_to_shared(Fh + r * 264 + col);
            asm volatile("ldmatrix.sync.aligned.m8n8.x4.shared.b16 {%0,%1,%2,%3}, [%4];"
                         : "=r"(a0), "=r"(a1), "=r"(a2), "=r"(a3) : "r"(addr));
        }
        #pragma unroll
        for (int fp = 0; fp < 4; fp++) {
            int n = wn * 64 + fp * 16 + ((lane >> 4) << 3) + (lane & 7);
            int k = kk * 16 + (((lane >> 3) & 1) << 3);
            uint32_t addr = (uint32_t)__cvta_generic_to_shared(Wt + n * 264 + k);
            uint32_t b0, b1, b2, b3;
            asm volatile("ldmatrix.sync.aligned.m8n8.x4.shared.b16 {%0,%1,%2,%3}, [%4];"
                         : "=r"(b0), "=r"(b1), "=r"(b2), "=r"(b3) : "r"(addr));
            asm volatile("mma.sync.aligned.m16n8k16.row.col.f32.f16.f16.f32 "
                         "{%0,%1,%2,%3}, {%4,%5,%6,%7}, {%8,%9}, {%0,%1,%2,%3};"
                         : "+f"(c[2 * fp][0]), "+f"(c[2 * fp][1]), "+f"(c[2 * fp][2]), "+f"(c[2 * fp][3])
                         : "r"(a0), "r"(a1), "r"(a2), "r"(a3), "r"(b0), "r"(b1));
            asm volatile("mma.sync.aligned.m16n8k16.row.col.f32.f16.f16.f32 "
                         "{%0,%1,%2,%3}, {%4,%5,%6,%7}, {%8,%9}, {%0,%1,%2,%3};"
                         : "+f"(c[2 * fp + 1][0]), "+f"(c[2 * fp + 1][1]), "+f"(c[2 * fp + 1][2]), "+f"(c[2 * fp + 1][3])
                         : "r"(a0), "r"(a1), "r"(a2), "r"(a3), "r"(b2), "r"(b3));
        }
    }

    // ---- bias + a2 partial dots ----
    const int r0 = wm * 16 + (lane >> 2);
    const int r1 = r0 + 8;
    float p0 = 0.f, p1 = 0.f;
    #pragma unroll
    for (int f = 0; f < 8; f++) {
        int col = wn * 64 + f * 8 + ((lane & 3) << 1);
        float b0v = bias[col], b1v = bias[col + 1];
        float aw0 = a2w[col],  aw1 = a2w[col + 1];
        c[f][0] += b0v; c[f][1] += b1v; c[f][2] += b0v; c[f][3] += b1v;
        p0 += c[f][0] * aw0 + c[f][1] * aw1;
        p1 += c[f][2] * aw0 + c[f][3] * aw1;
    }
    red[r0 * 8 + wn * 4 + (lane & 3)] = p0;
    red[r1 * 8 + wn * 4 + (lane & 3)] = p1;
    __syncthreads();   // also fences Fh reads before T alias-writes below
    if (tid < 64) {
        float s = 0.f;
        #pragma unroll
        for (int j = 0; j < 8; j++) s += red[tid * 8 + j];
        wrow[tid] = expf(s + a2b[0]);
    }
    __syncthreads();

    // ---- scale by w, transpose into T, store G^T ----
    const float w0v = wrow[r0], w1v = wrow[r1];
    #pragma unroll
    for (int f = 0; f < 8; f++) {
        int col = wn * 64 + f * 8 + ((lane & 3) << 1);
        T[(col)     * 72 + r0] = __float2half(c[f][0] * w0v);
        T[(col + 1) * 72 + r0] = __float2half(c[f][1] * w0v);
        T[(col)     * 72 + r1] = __float2half(c[f][2] * w1v);
        T[(col + 1) * 72 + r1] = __float2half(c[f][3] * w1v);
    }
    if (wn == 0 && (lane & 3) == 0) {
        T[128 * 72 + r0] = __float2half(w0v);
        T[128 * 72 + r1] = __float2half(w1v);
    }
    __syncthreads();
    // FIX: uint4 = 16 BYTES = 8 halves -> 8 chunks of 8 halves per 64-wide row.
    for (int cc = tid; cc < 129 * 8; cc += 256) {
        int rr = cc >> 3, off = (cc & 7) << 3;
        *(uint4*)(g_buf + (size_t)rr * NN + R + off) = *(const uint4*)(T + rr * 72 + off);
    }
}

// ---------------------------------------------------------------------------
// Kernel B: partial[64,160] = adj_fp16[64, 2048] @ G[2048,160], K-split x4,
// cp.async double-buffered for BOTH adj (int smem) and G.
// ---------------------------------------------------------------------------
__global__ void __launch_bounds__(256, 2) agg_kernel(const int* __restrict__ adj)
{
    extern __shared__ char smem[];
    int*    Ai = (int*)smem;                          // [2][64][68] ints (34816 B)
    __half* Bs = (__half*)(smem + 2 * 64 * 68 * 4);   // [2][160][72] halves (46080 B)

    const int tid  = threadIdx.x;
    const int lane = tid & 31;
    const int warp = tid >> 5;
    const int wm   = warp & 3;
    const int wn   = warp >> 2;
    const int R    = blockIdx.x * 64;
    const int spl  = blockIdx.y;
    const int kt0  = spl * TPK;

    float c[10][4];
    #pragma unroll
    for (int f = 0; f < 10; f++)
        #pragma unroll
        for (int j = 0; j < 4; j++) c[f][j] = 0.f;

    auto issue = [&](int tl) {
        const int kt = kt0 + tl;
        const int buf = tl & 1;
        // adj tile: 64 rows x 64 ints = 1024 x 16B chunks
        #pragma unroll
        for (int i = 0; i < 4; i++) {
            int cc = tid + i * 256;
            int r = cc >> 4, ch = cc & 15;
            const int* src = adj + (size_t)(R + r) * NN + kt * 64 + ch * 4;
            uint32_t dst = (uint32_t)__cvta_generic_to_shared(Ai + buf * 64 * 68 + r * 68 + ch * 4);
            asm volatile("cp.async.cg.shared.global [%0], [%1], 16;\n" :: "r"(dst), "l"(src));
        }
        // G tile: 160 rows x 64 halves = 1280 x 16B chunks
        #pragma unroll
        for (int i = 0; i < 5; i++) {
            int cc = tid + i * 256;
            int n = cc >> 3, ch = cc & 7;
            const __half* src = g_buf + (size_t)n * NN + kt * 64 + ch * 8;
            uint32_t dst = (uint32_t)__cvta_generic_to_shared(Bs + buf * 160 * 72 + n * 72 + ch * 8);
            asm volatile("cp.async.cg.shared.global [%0], [%1], 16;\n" :: "r"(dst), "l"(src));
        }
        asm volatile("cp.async.commit_group;\n" ::: "memory");
    };

    issue(0);

    const int grp = lane >> 2;
    const int c2  = (lane & 3) << 1;

    for (int t = 0; t < TPK; t++) {
        asm volatile("cp.async.wait_group 0;\n" ::: "memory");
        __syncthreads();
        if (t + 1 < TPK) issue(t + 1);

        const int buf = t & 1;
        const int* Ab = Ai + buf * 64 * 68;
        const __half* Bb = Bs + buf * 160 * 72;
        const int* Arow0 = Ab + (wm * 16 + grp) * 68 + c2;
        const int* Arow1 = Arow0 + 8 * 68;

        #pragma unroll
        for (int kk = 0; kk < 4; kk++) {
            const int ko = kk * 16;
            int2 p00 = *(const int2*)(Arow0 + ko);
            int2 p01 = *(const int2*)(Arow0 + ko + 8);
            int2 p10 = *(const int2*)(Arow1 + ko);
            int2 p11 = *(const int2*)(Arow1 + ko + 8);
            // adj values are exactly 0/1 -> fp16 1.0 = 0x3C00
            uint32_t a0 = (uint32_t)(p00.x + (p00.y << 16)) * 0x3C00u;
            uint32_t a1 = (uint32_t)(p10.x + (p10.y << 16)) * 0x3C00u;
            uint32_t a2 = (uint32_t)(p01.x + (p01.y << 16)) * 0x3C00u;
            uint32_t a3 = (uint32_t)(p11.x + (p11.y << 16)) * 0x3C00u;

            #pragma unroll
            for (int fp = 0; fp < 5; fp++) {
                int n = wn * 80 + fp * 16 + ((lane >> 4) << 3) + (lane & 7);
                int k = kk * 16 + (((lane >> 3) & 1) << 3);
                uint32_t addr = (uint32_t)__cvta_generic_to_shared(Bb + n * 72 + k);
                uint32_t b0, b1, b2, b3;
                asm volatile("ldmatrix.sync.aligned.m8n8.x4.shared.b16 {%0,%1,%2,%3}, [%4];"
                             : "=r"(b0), "=r"(b1), "=r"(b2), "=r"(b3) : "r"(addr));
                asm volatile("mma.sync.aligned.m16n8k16.row.col.f32.f16.f16.f32 "
                             "{%0,%1,%2,%3}, {%4,%5,%6,%7}, {%8,%9}, {%0,%1,%2,%3};"
                             : "+f"(c[2 * fp][0]), "+f"(c[2 * fp][1]), "+f"(c[2 * fp][2]), "+f"(c[2 * fp][3])
                             : "r"(a0), "r"(a1), "r"(a2), "r"(a3), "r"(b0), "r"(b1));
                asm volatile("mma.sync.aligned.m16n8k16.row.col.f32.f16.f16.f32 "
                             "{%0,%1,%2,%3}, {%4,%5,%6,%7}, {%8,%9}, {%0,%1,%2,%3};"
                             : "+f"(c[2 * fp + 1][0]), "+f"(c[2 * fp + 1][1]), "+f"(c[2 * fp + 1][2]), "+f"(c[2 * fp + 1][3])
                             : "r"(a0), "r"(a1), "r"(a2), "r"(a3), "r"(b2), "r"(b3));
            }
        }
    }

    // epilogue: write partials (cols 0..128) to workspace
    const int r0 = wm * 16 + (lane >> 2);
    const int r1 = r0 + 8;
    float* w0 = ws + ((size_t)spl * NN + R + r0) * WSTR;
    float* w1 = ws + ((size_t)spl * NN + R + r1) * WSTR;
    #pragma unroll
    for (int f = 0; f < 10; f++) {
        int col = wn * 80 + f * 8 + ((lane & 3) << 1);
        if (col <= 128) {
            *(float2*)(w0 + col) = make_float2(c[f][0], c[f][1]);
            *(float2*)(w1 + col) = make_float2(c[f][2], c[f][3]);
        }
    }
}

// ---------------------------------------------------------------------------
// Kernel C: out[i][c] = sum_s ws[s][i][c] / sum_s ws[s][i][128]
// ---------------------------------------------------------------------------
__global__ void __launch_bounds__(256) reduce_kernel(float* __restrict__ out)
{
    const int tid = threadIdx.x;
    const int row = blockIdx.x * 8 + (tid >> 5);
    const int c4  = (tid & 31) << 2;
    float4 a = make_float4(0.f, 0.f, 0.f, 0.f);
    float den = 0.f;
    #pragma unroll
    for (int s = 0; s < KS; s++) {
        const float* p = ws + ((size_t)s * NN + row) * WSTR;   // WSTR%4==0 -> 16B aligned
        float4 v = *(const float4*)(p + c4);
        a.x += v.x; a.y += v.y; a.z += v.z; a.w += v.w;
        den += p[128];
    }
    const float inv = 1.f / den;
    *(float4*)(out + (size_t)row * OUTF + c4) =
        make_float4(a.x * inv, a.y * inv, a.z * inv, a.w * inv);
}

// ---------------------------------------------------------------------------
extern "C" void kernel_launch(void* const* d_in, const int* in_sizes, int n_in,
                              void* d_out, int out_size) {
    (void)in_sizes; (void)n_in; (void)out_size;
    const float* feat = (const float*)d_in[0];
    const int*   adj  = (const int*)d_in[1];
    const float* W    = (const float*)d_in[2];
    const float* b    = (const float*)d_in[3];
    // a1_w / a1_b cancel in the row softmax and are unused.
    const float* a2w  = (const float*)d_in[6];
    const float* a2b  = (const float*)d_in[7];
    float* out = (float*)d_out;

    const int proj_smem = 33792 + 67584 + 64 * 8 * 4 + 64 * 4;  // 103680
    cudaFuncSetAttribute(proj_kernel, cudaFuncAttributeMaxDynamicSharedMemorySize, proj_smem);
    proj_kernel<<<NN / 64, 256, proj_smem>>>(feat, W, b, a2w, a2b);

    const int agg_smem = 2 * 64 * 68 * 4 + 2 * 160 * 72 * 2;    // 80896
    cudaFuncSetAttribute(agg_kernel, cudaFuncAttributeMaxDynamicSharedMemorySize, agg_smem);
    agg_kernel<<<dim3(NN / 64, KS), 256, agg_smem>>>(adj);

    reduce_kernel<<<NN / 8, 256>>>(out);
}